// round 12
// baseline (speedup 1.0000x reference)
#include <cuda_runtime.h>
#include <cuda_bf16.h>
#include <cstdint>

#define BB 4
#define NPTS 16384
#define NT 512
#define NTILES 2048

__device__ float g_T[BB * NPTS * 68];
__device__ __align__(16) unsigned char g_W[94208];

#define BH1 0
#define BL1 11264
#define BH2 22528
#define BL2 31744
#define BH3 40960
#define BL3 50176
#define BH4 59392
#define BL4 76800
#define WBYTES 94208

// SMEM (bytes)
#define SM_B    0
#define SM_BIAS 94208
#define SM_X0   95232      // 128 x 336B
#define SM_X1   138240     // 128 x 336B (L1 input / L2 out)
#define SM_F2   181248     // 128 x 336B feat2d hi|lo
#define SM_SCR  224256     // 512 floats corr partials
#define SMEM_TOTAL 226304
#define STRIDE 336
#define LOOFF  160

__device__ __forceinline__ uint32_t smem_u32(const void* p) {
    uint32_t a;
    asm("{ .reg .u64 t; cvta.to.shared.u64 t, %1; cvt.u32.u64 %0, t; }" : "=r"(a) : "l"(p));
    return a;
}
#define PBAR(id) asm volatile("bar.sync %0, 64;" :: "r"(id) : "memory")
#define LDSM4(r0, r1, r2, r3, addr) \
    asm volatile("ldmatrix.sync.aligned.m8n8.x4.shared.b16 {%0,%1,%2,%3}, [%4];" \
                 : "=r"(r0), "=r"(r1), "=r"(r2), "=r"(r3) : "r"(addr))
#define MMA16816(c, a0, a1, a2, a3, b0, b1) \
    asm volatile("mma.sync.aligned.m16n8k16.row.col.f32.bf16.bf16.f32 " \
                 "{%0,%1,%2,%3}, {%4,%5,%6,%7}, {%8,%9}, {%0,%1,%2,%3};" \
                 : "+f"((c)[0]), "+f"((c)[1]), "+f"((c)[2]), "+f"((c)[3]) \
                 : "r"(a0), "r"(a1), "r"(a2), "r"(a3), "r"(b0), "r"(b1))

__device__ __forceinline__ uint32_t pack2(float x, float y) {
    unsigned short a = __bfloat16_as_ushort(__float2bfloat16_rn(x));
    unsigned short b = __bfloat16_as_ushort(__float2bfloat16_rn(y));
    return (uint32_t)a | ((uint32_t)b << 16);
}
__device__ __forceinline__ float lo_of(float x) {
    return x - __bfloat162float(__float2bfloat16_rn(x));
}
__device__ __forceinline__ float lrelu(float v) { return fmaxf(v, 0.1f * v); }

// 4 MMAs: one A-frag x warp's 4 N-blocks (M16)
__device__ __forceinline__ void mma4(float* acc, const uint32_t* A, const uint32_t Bq[2][4]) {
#pragma unroll
    for (int nt = 0; nt < 4; nt++) {
        uint32_t b0 = Bq[nt >> 1][(nt & 1) << 1], b1 = Bq[nt >> 1][((nt & 1) << 1) + 1];
        MMA16816(acc + nt * 4, A[0], A[1], A[2], A[3], b0, b1);
    }
}
#define LOADB(Bq, addr, strB) do { \
    LDSM4(Bq[0][0], Bq[0][1], Bq[0][2], Bq[0][3], (addr)); \
    LDSM4(Bq[1][0], Bq[1][1], Bq[1][2], Bq[1][3], (addr) + 16u * (strB)); } while (0)

// j-step, A from SMEM (hi at a, lo at a+LOOFF)
__device__ __forceinline__ void smem_step(float* acc, uint32_t a, uint32_t bh, uint32_t bl,
                                          uint32_t strB) {
    uint32_t Ah[4], Al[4], Bh[2][4], Bl[2][4];
    LDSM4(Ah[0], Ah[1], Ah[2], Ah[3], a);
    LDSM4(Al[0], Al[1], Al[2], Al[3], a + LOOFF);
    LOADB(Bh, bh, strB); LOADB(Bl, bl, strB);
    mma4(acc, Ah, Bh); mma4(acc, Al, Bh); mma4(acc, Ah, Bl);
}
// j-step, A from registers (own channels)
__device__ __forceinline__ void reg_step(float* acc, const uint32_t* fh, const uint32_t* fl,
                                         uint32_t bh, uint32_t bl, uint32_t strB) {
    uint32_t Bh[2][4], Bl[2][4];
    LOADB(Bh, bh, strB); LOADB(Bl, bl, strB);
    mma4(acc, fh, Bh); mma4(acc, fl, Bh); mma4(acc, fh, Bl);
}

// bias+lrelu; build own next-layer A-frags in regs AND store own cols to X
__device__ __forceinline__ void epi_frags(const float* acc, const float* bias,
        uint32_t fh[2][4], uint32_t fl[2][4], char* Xg, int lane, int nBase) {
    const int r = lane >> 2, nb = (lane & 3) << 1;
#pragma unroll
    for (int nt = 0; nt < 4; nt++) {
        const float* c = acc + nt * 4;
        const int n = nBase + (nt << 3) + nb;
        float b0 = bias[n], b1 = bias[n + 1];
        float y0 = lrelu(c[0] + b0), y1 = lrelu(c[1] + b1);
        float y2 = lrelu(c[2] + b0), y3 = lrelu(c[3] + b1);
        uint32_t h01 = pack2(y0, y1), h23 = pack2(y2, y3);
        uint32_t l01 = pack2(lo_of(y0), lo_of(y1)), l23 = pack2(lo_of(y2), lo_of(y3));
        const int jp = nt >> 1, e = (nt & 1) << 1;
        fh[jp][e] = h01; fh[jp][e + 1] = h23;
        fl[jp][e] = l01; fl[jp][e + 1] = l23;
        char* p0 = Xg + r * STRIDE + n * 2;
        char* p1 = p0 + 8 * STRIDE;
        *(uint32_t*)p0 = h01; *(uint32_t*)(p0 + LOOFF) = l01;
        *(uint32_t*)p1 = h23; *(uint32_t*)(p1 + LOOFF) = l23;
    }
}

// ---------------- prep (unchanged, proven) ----------------
__global__ void prep_kernel(const float* __restrict__ xy, const float* __restrict__ feat3d,
                            const float* __restrict__ flow3d,
                            const float* __restrict__ w1, const float* __restrict__ w2,
                            const float* __restrict__ w3, const float* __restrict__ wf) {
    const int blk = blockIdx.x, tid = threadIdx.x;
    if (blk < 1024) {
        __shared__ float sT[68 * 67];
        const int b = blk >> 8, p0 = (blk & 255) << 6;
        const float* f3 = feat3d + (size_t)b * 64 * NPTS + p0;
#pragma unroll
        for (int it = 0; it < 16; it++) {
            int i = it * 256 + tid, c = i >> 6, pt = i & 63;
            sT[c * 67 + pt] = f3[(size_t)c * NPTS + pt];
        }
        if (tid < 128) {
            int c = tid >> 6, pt = tid & 63;
            sT[(64 + c) * 67 + pt] = flow3d[((size_t)b * 2 + c) * NPTS + p0 + pt];
            sT[(66 + c) * 67 + pt] = xy[((size_t)b * 2 + c) * NPTS + p0 + pt];
        }
        __syncthreads();
        float* dst = g_T + ((size_t)(b << 14) + p0) * 68;
#pragma unroll
        for (int it = 0; it < 17; it++) {
            int i = it * 256 + tid, pt = i / 68, c = i - pt * 68;
            dst[i] = sT[c * 67 + pt];
        }
    } else {
        int i = (blk - 1024) * 256 + tid;
        int n = i / 368, c = i - n * 368, l, k;
        if (c < 88)       { l = 0; k = c; }
        else if (c < 160) { l = 1; k = c - 88; }
        else if (c < 232) { l = 2; k = c - 160; }
        else              { l = 3; k = c - 232; }
        const int KR[4] = {69, 64, 64, 128}, STR[4] = {176, 144, 144, 272};
        const int BH[4] = {BH1, BH2, BH3, BH4}, BL[4] = {BL1, BL2, BL3, BL4};
        const float* src = (l == 0) ? w1 : (l == 1) ? w2 : (l == 2) ? w3 : wf;
        float v = (k < KR[l]) ? src[n * KR[l] + k] : 0.0f;
        int col = (l == 0) ? ((k < 3) ? k : k + 1) : k;
        float hf = __bfloat162float(__float2bfloat16_rn(v));
        unsigned short hb = __bfloat16_as_ushort(__float2bfloat16_rn(v));
        unsigned short lb = __bfloat16_as_ushort(__float2bfloat16_rn(v - hf));
        if (col * 2 < STR[l]) {
            int off = n * STR[l] + col * 2;
            *(unsigned short*)(g_W + BH[l] + off) = hb;
            *(unsigned short*)(g_W + BL[l] + off) = lb;
        }
        if (l == 0 && k == 87) {
            int off = n * 176 + 6;
            *(unsigned short*)(g_W + BH1 + off) = 0;
            *(unsigned short*)(g_W + BL1 + off) = 0;
        }
    }
}

// ---------------- fused: 16 warps, M16N32, reg-resident own half ----------------
__global__ __launch_bounds__(NT, 1)
void fused_kernel(const float* __restrict__ feat2d, const float* __restrict__ lf2d,
                  const int* __restrict__ nnp,
                  const float* __restrict__ b1, const float* __restrict__ b2,
                  const float* __restrict__ b3, const float* __restrict__ bfin,
                  float* __restrict__ out) {
    extern __shared__ char smem[];
    const uint32_t s32 = smem_u32(smem);
    const int tid = threadIdx.x, lane = tid & 31, wid = tid >> 5;
    const int grp = wid >> 1, warpPix = grp << 4;   // 8 groups x 16 px
    const int nh = wid & 1, nBase = nh << 5;
    const int barid = 1 + grp;                      // 1..8
    const int pl = tid & 127, q = tid >> 7;         // prologue: pixel, channel quarter

    {   // one-time weight copy
        const uint4* src = (const uint4*)g_W;
        uint4* dst = (uint4*)(smem + SM_B);
        for (int i = tid; i < WBYTES / 16; i += NT) dst[i] = src[i];
        float* sb = (float*)(smem + SM_BIAS);
        if (tid < 64) {
            sb[tid] = b1[tid]; sb[64 + tid] = b2[tid];
            sb[128 + tid] = b3[tid]; sb[192 + tid] = bfin[tid];
        }
    }
    __syncthreads();
    const float* sbias = (const float*)(smem + SM_BIAS);
    float* scr = (float*)(smem + SM_SCR);

    // lane-derived fragment addresses
    const int g = lane >> 3, r8 = lane & 7;
    const int aRow = ((g & 1) << 3) + r8, aColB = (g >> 1) << 4;
    const int bRow = ((g >> 1) << 3) + r8, bColB = (g & 1) << 4;
    const uint32_t rowOff = (uint32_t)(warpPix + aRow) * STRIDE + aColB;
    const uint32_t aX0 = s32 + SM_X0 + rowOff;
    const uint32_t aX1 = s32 + SM_X1 + rowOff;
    const uint32_t aF2 = s32 + SM_F2 + rowOff;
    const uint32_t brow = (uint32_t)(nBase + bRow);
    const uint32_t bh1 = s32 + SM_B + BH1 + brow * 176 + bColB;
    const uint32_t bl1 = s32 + SM_B + BL1 + brow * 176 + bColB;
    const uint32_t bh2 = s32 + SM_B + BH2 + brow * 144 + bColB;
    const uint32_t bl2 = s32 + SM_B + BL2 + brow * 144 + bColB;
    const uint32_t bh3 = s32 + SM_B + BH3 + brow * 144 + bColB;
    const uint32_t bl3 = s32 + SM_B + BL3 + brow * 144 + bColB;
    const uint32_t bh4 = s32 + SM_B + BH4 + brow * 272 + bColB;
    const uint32_t bl4 = s32 + SM_B + BL4 + brow * 272 + bColB;
    const uint32_t ownB = (uint32_t)nBase * 2;       // own channels' k-byte base
    const uint32_t sibB = (uint32_t)(nh ? 0 : 64);   // sibling channels' k-byte base
    char* Xg0 = smem + SM_X0 + warpPix * STRIDE;
    char* Xg1 = smem + SM_X1 + warpPix * STRIDE;

    for (int tile = blockIdx.x; tile < NTILES; tile += gridDim.x) {
        const int gp = (tile << 7) + pl;
        const int b = gp >> 16, pix = gp & 65535;

        {   // prologue: thread (pl, q) = pixel pl, channels [16q, 16q+16)
            const int idx = nnp[gp];
            const float* t3 = g_T + (size_t)((b << 14) + idx) * 68;
            float av[16];
            const float* t3h = t3 + (q << 4);
#pragma unroll
            for (int k = 0; k < 16; k += 4) {
                float4 v = *(const float4*)(t3h + k);
                av[k] = v.x; av[k + 1] = v.y; av[k + 2] = v.z; av[k + 3] = v.w;
            }
            float4 tv = make_float4(0.f, 0.f, 0.f, 0.f);
            float lfx = 0.f, lfy = 0.f;
            if (q == 3) {
                tv = *(const float4*)(t3 + 64);
                const float* lf = lf2d + (((size_t)b * 2) << 16) + pix;
                lfx = lf[0]; lfy = lf[65536];
            }
            char* F2p = smem + SM_F2 + pl * STRIDE;
            const float* f2p = feat2d + (((size_t)(b * 64 + (q << 4))) << 16) + pix;
            float pc = 0.0f;
#pragma unroll
            for (int c = 0; c < 16; c += 2) {
                float v0 = f2p[(size_t)c << 16], v1 = f2p[(size_t)(c + 1) << 16];
                pc += av[c] * v0 + av[c + 1] * v1;
                *(uint32_t*)(F2p + (q << 5) + c * 2) = pack2(v0, v1);
                *(uint32_t*)(F2p + LOOFF + (q << 5) + c * 2) = pack2(lo_of(v0), lo_of(v1));
            }
            char* A1p = smem + SM_X1 + pl * STRIDE;
#pragma unroll
            for (int k = 0; k < 16; k += 2) {
                int cb = (4 + (q << 4) + k) * 2;
                *(uint32_t*)(A1p + cb) = pack2(av[k], av[k + 1]);
                *(uint32_t*)(A1p + LOOFF + cb) = pack2(lo_of(av[k]), lo_of(av[k + 1]));
            }
            scr[tid] = pc;
            __syncthreads();
            if (q == 3) {
                float corr = (scr[pl] + scr[pl + 128] + scr[pl + 256] + pc) * (1.0f / 64.0f);
                float offx = tv.z - (float)(pix & 255);
                float offy = tv.w - (float)(pix >> 8);
                float fl0v = tv.x - lfx, fl1v = tv.y - lfy;
                *(uint32_t*)(A1p + 0) = pack2(corr, offx);
                *(uint32_t*)(A1p + 4) = pack2(offy, 0.0f);
                *(uint32_t*)(A1p + 160) = pack2(lo_of(corr), lo_of(offx));
                *(uint32_t*)(A1p + 164) = pack2(lo_of(offy), 0.0f);
                *(uint32_t*)(A1p + 136) = pack2(fl0v, fl1v);
                *(uint32_t*)(A1p + 296) = pack2(lo_of(fl0v), lo_of(fl1v));
#pragma unroll
                for (int z = 0; z < 5; z++) {
                    *(uint32_t*)(A1p + 140 + z * 4) = 0u;
                    *(uint32_t*)(A1p + 300 + z * 4) = 0u;
                }
            }
        }
        __syncthreads();

        float acc[16];
        uint32_t fh[2][4], fl[2][4];

        // ---- layer 1: K=80, all A from X1 ----
#pragma unroll
        for (int i = 0; i < 16; i++) acc[i] = 0.0f;
#pragma unroll
        for (int j = 0; j < 5; j++)
            smem_step(acc, aX1 + j * 32, bh1 + j * 32, bl1 + j * 32, 176);
        epi_frags(acc, sbias, fh, fl, Xg0, lane, nBase);
        PBAR(barid);

        // ---- layer 2: own regs + sibling X0 ----
#pragma unroll
        for (int i = 0; i < 16; i++) acc[i] = 0.0f;
#pragma unroll
        for (int j = 0; j < 2; j++)
            reg_step(acc, fh[j], fl[j], bh2 + ownB + j * 32, bl2 + ownB + j * 32, 144);
#pragma unroll
        for (int j = 0; j < 2; j++)
            smem_step(acc, aX0 + sibB + j * 32, bh2 + sibB + j * 32, bl2 + sibB + j * 32, 144);
        epi_frags(acc, sbias + 64, fh, fl, Xg1, lane, nBase);
        PBAR(barid);

        // ---- layer 3: own regs + sibling X1 ----
#pragma unroll
        for (int i = 0; i < 16; i++) acc[i] = 0.0f;
#pragma unroll
        for (int j = 0; j < 2; j++)
            reg_step(acc, fh[j], fl[j], bh3 + ownB + j * 32, bl3 + ownB + j * 32, 144);
#pragma unroll
        for (int j = 0; j < 2; j++)
            smem_step(acc, aX1 + sibB + j * 32, bh3 + sibB + j * 32, bl3 + sibB + j * 32, 144);
        epi_frags(acc, sbias + 128, fh, fl, Xg0, lane, nBase);
        PBAR(barid);

        // ---- layer 4: K=128 = x3(own regs + sibling X0) | feat2d(F2) ----
#pragma unroll
        for (int i = 0; i < 16; i++) acc[i] = 0.0f;
#pragma unroll
        for (int j = 0; j < 2; j++)
            reg_step(acc, fh[j], fl[j], bh4 + ownB + j * 32, bl4 + ownB + j * 32, 272);
#pragma unroll
        for (int j = 0; j < 2; j++)
            smem_step(acc, aX0 + sibB + j * 32, bh4 + sibB + j * 32, bl4 + sibB + j * 32, 272);
#pragma unroll
        for (int j = 0; j < 4; j++)
            smem_step(acc, aF2 + j * 32, bh4 + 128 + j * 32, bl4 + 128 + j * 32, 272);

        // ---- output: direct STG ----
        {
            const int pixbase = (tile << 7) & 65535;
            const int r = lane >> 2, nb = (lane & 3) << 1;
            float* ob = out + ((size_t)b << 22) + pixbase;
            float* p0 = ob + warpPix + r;
            float* p1 = p0 + 8;
#pragma unroll
            for (int nt = 0; nt < 4; nt++) {
                const float* c = acc + nt * 4;
                const int n = nBase + (nt << 3) + nb;
                float bb0 = sbias[192 + n], bb1 = sbias[192 + n + 1];
                p0[(size_t)n << 16] = lrelu(c[0] + bb0);
                p0[(size_t)(n + 1) << 16] = lrelu(c[1] + bb1);
                p1[(size_t)n << 16] = lrelu(c[2] + bb0);
                p1[(size_t)(n + 1) << 16] = lrelu(c[3] + bb1);
            }
        }
        __syncthreads();   // X/F2 fully consumed before next prologue
    }
}

extern "C" void kernel_launch(void* const* d_in, const int* in_sizes, int n_in,
                              void* d_out, int out_size) {
    const float* xy   = (const float*)d_in[0];
    const float* f2d  = (const float*)d_in[1];
    const float* f3d  = (const float*)d_in[2];
    const float* lf2d = (const float*)d_in[3];
    const int*   nnp  = (const int*)d_in[5];
    const float* w1 = (const float*)d_in[6];
    const float* b1 = (const float*)d_in[7];
    const float* w2 = (const float*)d_in[8];
    const float* b2 = (const float*)d_in[9];
    const float* w3 = (const float*)d_in[10];
    const float* b3 = (const float*)d_in[11];
    const float* wf = (const float*)d_in[12];
    const float* bf = (const float*)d_in[13];
    float* out = (float*)d_out;

    cudaFuncSetAttribute(fused_kernel,
                         cudaFuncAttributeMaxDynamicSharedMemorySize, SMEM_TOTAL);
    prep_kernel<<<1024 + 92, 256>>>(xy, f3d, (const float*)d_in[4], w1, w2, w3, wf);
    fused_kernel<<<148, NT, SMEM_TOTAL>>>(f2d, lf2d, nnp, b1, b2, b3, bf, out);
}

// round 13
// speedup vs baseline: 1.1470x; 1.1470x over previous
#include <cuda_runtime.h>
#include <cuda_bf16.h>
#include <cstdint>

#define BB 4
#define NPTS 16384
#define NT 512
#define NTILES 2048

__device__ float g_T[BB * NPTS * 68];
__device__ float g_Y[BB * NPTS * 64];                 // precomputed per-point layer-1 partial
__device__ __align__(16) unsigned char g_W[94208];

// g_W source offsets (bytes)
#define BH1 0
#define BL1 11264
#define BH2 22528
#define BL2 31744
#define BH3 40960
#define BL3 50176
#define BH4 59392
#define BL4 76800
#define WBYTES 94208
// fused copies only [BH2, WBYTES): 71680 bytes; offsets within copy:
#define CPY_OFF 22528
#define CPY_BYTES 71680
#define oBH2 0
#define oBL2 9216
#define oBH3 18432
#define oBL3 27648
#define oBH4 36864
#define oBL4 54272

// fused SMEM (bytes)
#define SM_B    0          // 71680
#define SM_BIAS 71680      // 256 floats
#define SM_W1C  72704      // 5 x 64 floats (w1 cols 0,1,2,67,68)
#define SM_A1   73984      // 128 x 336B (L2/L3 activations hi|lo)
#define SM_A4   116992     // 128 x 528B (L4 input hi|lo)
#define SM_SCR  184576     // 512 floats
#define SMEM_TOTAL 186624

#define STRIDE_A1 336
#define STRIDE_A4 528

__device__ __forceinline__ uint32_t smem_u32(const void* p) {
    uint32_t a;
    asm("{ .reg .u64 t; cvta.to.shared.u64 t, %1; cvt.u32.u64 %0, t; }" : "=r"(a) : "l"(p));
    return a;
}
#define GBAR(id) asm volatile("bar.sync %0, 128;" :: "r"(id) : "memory")
#define LDSM4(r0, r1, r2, r3, addr) \
    asm volatile("ldmatrix.sync.aligned.m8n8.x4.shared.b16 {%0,%1,%2,%3}, [%4];" \
                 : "=r"(r0), "=r"(r1), "=r"(r2), "=r"(r3) : "r"(addr))
#define MMA16816(c, a0, a1, a2, a3, b0, b1) \
    asm volatile("mma.sync.aligned.m16n8k16.row.col.f32.bf16.bf16.f32 " \
                 "{%0,%1,%2,%3}, {%4,%5,%6,%7}, {%8,%9}, {%0,%1,%2,%3};" \
                 : "+f"((c)[0]), "+f"((c)[1]), "+f"((c)[2]), "+f"((c)[3]) \
                 : "r"(a0), "r"(a1), "r"(a2), "r"(a3), "r"(b0), "r"(b1))

__device__ __forceinline__ uint32_t pack2(float x, float y) {
    unsigned short a = __bfloat16_as_ushort(__float2bfloat16_rn(x));
    unsigned short b = __bfloat16_as_ushort(__float2bfloat16_rn(y));
    return (uint32_t)a | ((uint32_t)b << 16);
}
__device__ __forceinline__ float lo_of(float x) {
    return x - __bfloat162float(__float2bfloat16_rn(x));
}
__device__ __forceinline__ float lrelu(float v) { return fmaxf(v, 0.1f * v); }

// ---------------- prep: transpose + Y1p GEMM + weight split ----------------
__global__ void prep_kernel(const float* __restrict__ xy, const float* __restrict__ feat3d,
                            const float* __restrict__ flow3d,
                            const float* __restrict__ w1, const float* __restrict__ w2,
                            const float* __restrict__ w3, const float* __restrict__ wf,
                            const float* __restrict__ b1unused) {
    const int blk = blockIdx.x, tid = threadIdx.x;
    if (blk < 1024) {
        __shared__ float sT[68 * 67];
        __shared__ float wT[68 * 64];     // wT[k][n] = W1[n][colmap(k)]
        const int b = blk >> 8, p0 = (blk & 255) << 6;
        const float* f3 = feat3d + (size_t)b * 64 * NPTS + p0;
#pragma unroll
        for (int it = 0; it < 16; it++) {
            int i = it * 256 + tid, c = i >> 6, pt = i & 63;
            sT[c * 67 + pt] = f3[(size_t)c * NPTS + pt];
        }
        if (tid < 128) {
            int c = tid >> 6, pt = tid & 63;
            sT[(64 + c) * 67 + pt] = flow3d[((size_t)b * 2 + c) * NPTS + p0 + pt];
            sT[(66 + c) * 67 + pt] = xy[((size_t)b * 2 + c) * NPTS + p0 + pt];
        }
        // wT: T-row index k -> w1 column {k<64: 3+k, 64:67, 65:68, 66:1, 67:2}
#pragma unroll
        for (int it = 0; it < 17; it++) {
            int i = it * 256 + tid, k = i >> 6, n = i & 63;
            int cm = (k < 64) ? (3 + k) : (k == 64) ? 67 : (k == 65) ? 68 : (k == 66) ? 1 : 2;
            wT[i] = w1[n * 69 + cm];
        }
        __syncthreads();
        // write transposed table
        float* dst = g_T + ((size_t)(b << 14) + p0) * 68;
#pragma unroll
        for (int it = 0; it < 17; it++) {
            int i = it * 256 + tid, pt = i / 68, c = i - pt * 68;
            dst[i] = sT[c * 67 + pt];
        }
        // Y1p: point p, outputs [n0, n0+16)
        {
            const int p = tid & 63, n0 = (tid >> 6) << 4;
            float acc[16];
#pragma unroll
            for (int j = 0; j < 16; j++) acc[j] = 0.0f;
            for (int k = 0; k < 68; k++) {
                float x = sT[k * 67 + p];
                const float4* wv = (const float4*)(wT + k * 64 + n0);
#pragma unroll
                for (int j4 = 0; j4 < 4; j4++) {
                    float4 w = wv[j4];
                    acc[j4 * 4 + 0] += x * w.x; acc[j4 * 4 + 1] += x * w.y;
                    acc[j4 * 4 + 2] += x * w.z; acc[j4 * 4 + 3] += x * w.w;
                }
            }
            float4* yd = (float4*)(g_Y + ((size_t)((b << 14) + p0 + p)) * 64 + n0);
#pragma unroll
            for (int j4 = 0; j4 < 4; j4++)
                yd[j4] = make_float4(acc[j4 * 4], acc[j4 * 4 + 1], acc[j4 * 4 + 2], acc[j4 * 4 + 3]);
        }
    } else {
        int i = (blk - 1024) * 256 + tid;
        int n = i / 368, c = i - n * 368, l, k;
        if (c < 88)       { l = 0; k = c; }
        else if (c < 160) { l = 1; k = c - 88; }
        else if (c < 232) { l = 2; k = c - 160; }
        else              { l = 3; k = c - 232; }
        const int KR[4] = {69, 64, 64, 128}, STR[4] = {176, 144, 144, 272};
        const int BH[4] = {BH1, BH2, BH3, BH4}, BL[4] = {BL1, BL2, BL3, BL4};
        const float* src = (l == 0) ? w1 : (l == 1) ? w2 : (l == 2) ? w3 : wf;
        float v = (k < KR[l]) ? src[n * KR[l] + k] : 0.0f;
        int col = (l == 0) ? ((k < 3) ? k : k + 1) : k;
        float hf = __bfloat162float(__float2bfloat16_rn(v));
        unsigned short hb = __bfloat16_as_ushort(__float2bfloat16_rn(v));
        unsigned short lb = __bfloat16_as_ushort(__float2bfloat16_rn(v - hf));
        if (col * 2 < STR[l]) {
            int off = n * STR[l] + col * 2;
            *(unsigned short*)(g_W + BH[l] + off) = hb;
            *(unsigned short*)(g_W + BL[l] + off) = lb;
        }
    }
}

// ---------------- per-warp GEMM layer: M=32, N=16 (R9-proven) ----------------
__device__ __forceinline__ void run_layer(float* acc, uint32_t aBase, int strideA,
                                          int loAoff, int ksegs,
                                          uint32_t bHi, uint32_t bLo, int strideB,
                                          int lane, int warpPix, int nBase) {
    const int g = lane >> 3, r = lane & 7;
    const int aRow = ((g & 1) << 3) + r, aColB = (g >> 1) << 4;
    const int bRow = ((g >> 1) << 3) + r, bColB = (g & 1) << 4;
    const uint32_t aAddr = aBase + (uint32_t)(warpPix + aRow) * strideA + aColB;
    const uint32_t bhAddr = bHi + (uint32_t)(nBase + bRow) * strideB + bColB;
    const uint32_t blAddr = bLo + (uint32_t)(nBase + bRow) * strideB + bColB;
#pragma unroll
    for (int j = 0; j < ksegs; j++) {
        const uint32_t ja = (uint32_t)(j << 5);
        uint32_t Ah0[4], Ah1[4], Al0[4], Al1[4], Bh[4], Bl[4];
        LDSM4(Ah0[0], Ah0[1], Ah0[2], Ah0[3], aAddr + ja);
        LDSM4(Ah1[0], Ah1[1], Ah1[2], Ah1[3], aAddr + ja + 16u * strideA);
        LDSM4(Al0[0], Al0[1], Al0[2], Al0[3], aAddr + ja + loAoff);
        LDSM4(Al1[0], Al1[1], Al1[2], Al1[3], aAddr + ja + loAoff + 16u * strideA);
        LDSM4(Bh[0], Bh[1], Bh[2], Bh[3], bhAddr + ja);
        LDSM4(Bl[0], Bl[1], Bl[2], Bl[3], blAddr + ja);
#pragma unroll
        for (int nt = 0; nt < 2; nt++) {
            uint32_t bh0 = Bh[nt << 1], bh1 = Bh[(nt << 1) + 1];
            uint32_t bl0 = Bl[nt << 1], bl1 = Bl[(nt << 1) + 1];
            float* c0 = acc + nt * 4;
            float* c1 = acc + 8 + nt * 4;
            MMA16816(c0, Ah0[0], Ah0[1], Ah0[2], Ah0[3], bh0, bh1);
            MMA16816(c1, Ah1[0], Ah1[1], Ah1[2], Ah1[3], bh0, bh1);
            MMA16816(c0, Al0[0], Al0[1], Al0[2], Al0[3], bh0, bh1);
            MMA16816(c1, Al1[0], Al1[1], Al1[2], Al1[3], bh0, bh1);
            MMA16816(c0, Ah0[0], Ah0[1], Ah0[2], Ah0[3], bl0, bl1);
            MMA16816(c1, Ah1[0], Ah1[1], Ah1[2], Ah1[3], bl0, bl1);
        }
    }
}

__device__ __forceinline__ void epi_store(const float* acc, const float* bias,
                                          char* dst, int strideA, int loOffB,
                                          int lane, int warpPix, int nBase) {
    const int r = lane >> 2, nb = (lane & 3) << 1;
#pragma unroll
    for (int mt = 0; mt < 2; mt++) {
        char* p0 = dst + (warpPix + (mt << 4) + r) * strideA;
        char* p1 = p0 + 8 * strideA;
#pragma unroll
        for (int nt = 0; nt < 2; nt++) {
            const float* c = acc + mt * 8 + nt * 4;
            const int n = nBase + (nt << 3) + nb;
            float b0 = bias[n], b1 = bias[n + 1];
            float v00 = lrelu(c[0] + b0), v01 = lrelu(c[1] + b1);
            float v10 = lrelu(c[2] + b0), v11 = lrelu(c[3] + b1);
            *(uint32_t*)(p0 + n * 2)          = pack2(v00, v01);
            *(uint32_t*)(p0 + loOffB + n * 2) = pack2(lo_of(v00), lo_of(v01));
            *(uint32_t*)(p1 + n * 2)          = pack2(v10, v11);
            *(uint32_t*)(p1 + loOffB + n * 2) = pack2(lo_of(v10), lo_of(v11));
        }
    }
}

// ---------------- fused: 16 warps (4 groups x 4 N-quarters), L1 via Y1p ----------------
__global__ __launch_bounds__(NT, 1)
void fused_kernel(const float* __restrict__ feat2d, const float* __restrict__ lf2d,
                  const int* __restrict__ nnp,
                  const float* __restrict__ w1,
                  const float* __restrict__ b1, const float* __restrict__ b2,
                  const float* __restrict__ b3, const float* __restrict__ bfin,
                  float* __restrict__ out) {
    extern __shared__ char smem[];
    const uint32_t s32 = smem_u32(smem);
    const int tid = threadIdx.x, lane = tid & 31, wid = tid >> 5;
    const int grp = wid >> 2, warpPix = grp << 5;
    const int nBase = (wid & 3) << 4;
    const int barid = 1 + grp;
    const int t = tid & 127, p32 = t & 31, q = t >> 5;
    const int prow = ((tid >> 7) << 5) + p32;          // prologue pixel (same group as barid)

    {   // one-time: weights (L2..L4 only) + bias + w1 per-pixel columns
        const uint4* src = (const uint4*)(g_W + CPY_OFF);
        uint4* dst = (uint4*)(smem + SM_B);
        for (int i = tid; i < CPY_BYTES / 16; i += NT) dst[i] = src[i];
        float* sb = (float*)(smem + SM_BIAS);
        float* wc = (float*)(smem + SM_W1C);
        if (tid < 64) {
            sb[tid] = b1[tid]; sb[64 + tid] = b2[tid];
            sb[128 + tid] = b3[tid]; sb[192 + tid] = bfin[tid];
            wc[tid]       = w1[tid * 69 + 0];
            wc[64 + tid]  = w1[tid * 69 + 1];
            wc[128 + tid] = w1[tid * 69 + 2];
            wc[192 + tid] = w1[tid * 69 + 67];
            wc[256 + tid] = w1[tid * 69 + 68];
        }
    }
    __syncthreads();
    const float* sbias = (const float*)(smem + SM_BIAS);
    const float* w1c = (const float*)(smem + SM_W1C);
    float* scr = (float*)(smem + SM_SCR);

    const uint32_t aA1 = s32 + SM_A1, aA4 = s32 + SM_A4;
    const uint32_t wb = s32 + SM_B;

    for (int tile = blockIdx.x; tile < NTILES; tile += gridDim.x) {
        const int gp = (tile << 7) + prow;
        const int b = gp >> 16, pix = gp & 65535;

        // ---------- prologue: thread (prow, q) = channels [16q, 16q+16) ----------
        {
            const int idx = nnp[gp];
            const int pr = (b << 14) + idx;
            // feats for corr
            float av[16];
            const float* t3h = g_T + (size_t)pr * 68 + (q << 4);
#pragma unroll
            for (int k = 0; k < 16; k += 4) {
                float4 v = *(const float4*)(t3h + k);
                av[k] = v.x; av[k + 1] = v.y; av[k + 2] = v.z; av[k + 3] = v.w;
            }
            // Y1p slice
            float y1p[16];
            const float4* yp = (const float4*)(g_Y + (size_t)pr * 64 + (q << 4));
#pragma unroll
            for (int j4 = 0; j4 < 4; j4++) {
                float4 v = yp[j4];
                y1p[j4 * 4] = v.x; y1p[j4 * 4 + 1] = v.y;
                y1p[j4 * 4 + 2] = v.z; y1p[j4 * 4 + 3] = v.w;
            }
            const float* lf = lf2d + (((size_t)b * 2) << 16) + pix;
            const float lfx = lf[0], lfy = lf[65536];

            // f2 -> A4 (hi @128, lo @384) + corr partial
            char* A4p = smem + SM_A4 + prow * STRIDE_A4;
            const float* f2p = feat2d + (((size_t)(b * 64 + (q << 4))) << 16) + pix;
            float pc = 0.0f;
#pragma unroll
            for (int c = 0; c < 16; c += 2) {
                float v0 = f2p[(size_t)c << 16], v1 = f2p[(size_t)(c + 1) << 16];
                pc += av[c] * v0 + av[c + 1] * v1;
                *(uint32_t*)(A4p + 128 + (q << 5) + c * 2) = pack2(v0, v1);
                *(uint32_t*)(A4p + 384 + (q << 5) + c * 2) = pack2(lo_of(v0), lo_of(v1));
            }
            scr[tid] = pc;
            GBAR(barid);
            const int b0i = (grp << 7) + p32;
            const float corr = (scr[b0i] + scr[b0i + 32] + scr[b0i + 64] + scr[b0i + 96])
                               * (1.0f / 64.0f);
            const float swi = -(float)(pix & 255), shi = -(float)(pix >> 8);

            // y1 = lrelu(Y1p + corr*w0 + swi*w1 + shi*w2 - lfx*w67 - lfy*w68 + b1)  [exact fp32]
            char* A1p = smem + SM_A1 + prow * STRIDE_A1;
#pragma unroll
            for (int j = 0; j < 16; j += 2) {
                const int c = (q << 4) + j;
                float ya = y1p[j]     + corr * w1c[c]     + swi * w1c[64 + c]
                         + shi * w1c[128 + c]     - lfx * w1c[192 + c]
                         - lfy * w1c[256 + c]     + sbias[c];
                float yb = y1p[j + 1] + corr * w1c[c + 1] + swi * w1c[64 + c + 1]
                         + shi * w1c[128 + c + 1] - lfx * w1c[192 + c + 1]
                         - lfy * w1c[256 + c + 1] + sbias[c + 1];
                ya = lrelu(ya); yb = lrelu(yb);
                *(uint32_t*)(A1p + c * 2)       = pack2(ya, yb);
                *(uint32_t*)(A1p + 128 + c * 2) = pack2(lo_of(ya), lo_of(yb));
            }
        }
        GBAR(barid);

        float acc[16];

        // ---- layer 2: A1 -> A1 ----
#pragma unroll
        for (int i = 0; i < 16; i++) acc[i] = 0.0f;
        run_layer(acc, aA1, STRIDE_A1, 128, 4,
                  wb + oBH2, wb + oBL2, 144, lane, warpPix, nBase);
        GBAR(barid);   // reads complete before overwrite
        epi_store(acc, sbias + 64, smem + SM_A1, STRIDE_A1, 128, lane, warpPix, nBase);
        GBAR(barid);

        // ---- layer 3: A1 -> A4 (x3 region; disjoint, no pre-epi barrier) ----
#pragma unroll
        for (int i = 0; i < 16; i++) acc[i] = 0.0f;
        run_layer(acc, aA1, STRIDE_A1, 128, 4,
                  wb + oBH3, wb + oBL3, 144, lane, warpPix, nBase);
        epi_store(acc, sbias + 128, smem + SM_A4, STRIDE_A4, 256, lane, warpPix, nBase);
        GBAR(barid);

        // ---- layer 4: K=128 from A4 ----
#pragma unroll
        for (int i = 0; i < 16; i++) acc[i] = 0.0f;
        run_layer(acc, aA4, STRIDE_A4, 256, 8,
                  wb + oBH4, wb + oBL4, 272, lane, warpPix, nBase);

        // ---- output: direct STG ----
        {
            const int pixbase = (tile << 7) & 65535;
            const int r = lane >> 2, nb = (lane & 3) << 1;
            float* ob = out + ((size_t)b << 22) + pixbase;
#pragma unroll
            for (int mt = 0; mt < 2; mt++) {
                float* p0 = ob + warpPix + (mt << 4) + r;
                float* p1 = p0 + 8;
#pragma unroll
                for (int nt = 0; nt < 2; nt++) {
                    const float* c = acc + mt * 8 + nt * 4;
                    const int n = nBase + (nt << 3) + nb;
                    float bb0 = sbias[192 + n], bb1 = sbias[192 + n + 1];
                    p0[(size_t)n << 16] = lrelu(c[0] + bb0);
                    p0[(size_t)(n + 1) << 16] = lrelu(c[1] + bb1);
                    p1[(size_t)n << 16] = lrelu(c[2] + bb0);
                    p1[(size_t)(n + 1) << 16] = lrelu(c[3] + bb1);
                }
            }
        }
        GBAR(barid);   // A1/A4 consumed before next prologue
    }
}

extern "C" void kernel_launch(void* const* d_in, const int* in_sizes, int n_in,
                              void* d_out, int out_size) {
    const float* xy   = (const float*)d_in[0];
    const float* f2d  = (const float*)d_in[1];
    const float* f3d  = (const float*)d_in[2];
    const float* lf2d = (const float*)d_in[3];
    const float* lf3d = (const float*)d_in[4];
    const int*   nnp  = (const int*)d_in[5];
    const float* w1 = (const float*)d_in[6];
    const float* b1 = (const float*)d_in[7];
    const float* w2 = (const float*)d_in[8];
    const float* b2 = (const float*)d_in[9];
    const float* w3 = (const float*)d_in[10];
    const float* b3 = (const float*)d_in[11];
    const float* wf = (const float*)d_in[12];
    const float* bf = (const float*)d_in[13];
    float* out = (float*)d_out;

    cudaFuncSetAttribute(fused_kernel,
                         cudaFuncAttributeMaxDynamicSharedMemorySize, SMEM_TOTAL);
    prep_kernel<<<1024 + 92, 256>>>(xy, f3d, lf3d, w1, w2, w3, wf, b1);
    fused_kernel<<<148, NT, SMEM_TOTAL>>>(f2d, lf2d, nnp, w1, b1, b2, b3, bf, out);
}